// round 11
// baseline (speedup 1.0000x reference)
#include <cuda_runtime.h>
#include <cuda_fp16.h>
#include <cstdint>

// ============================================================================
// y[M,N] = x[M,K] @ W[N,K]^T * scaler ; x fp32, W int8 (delivered as int32),
// out fp32.
// Round 11: fp16 HMMA probe, FIXED prep (R10's x-conversion was a buffer bug).
//   x -> fp16 (RN, rel err ~2.8e-4), W int8 -> fp16 EXACT.
//   Same mma count as the 2-plane int8 scheme; 2x win iff HMMA rt=8 vs IMMA 16.
// ============================================================================
#define M_TOTAL 8192
#define N_TOTAL 11008
#define K_TOTAL 4096
#define K2 (K_TOTAL * 2)          // row stride in bytes (fp16)

#define BM 64
#define BN 128
#define BKE 64                    // K elements per stage (128 bytes)
#define KITERS (K_TOTAL / BKE)    // 64
#define GRID_N (N_TOTAL / BN)     // 86
#define GRID_M (M_TOTAL / BM)     // 128
#define NTILES (GRID_N * GRID_M)  // 11008

#define NS 4                      // pipeline stages
#define PITCH 144                 // bytes/row: conflict-free LDS phases
#define A_TILE_BYTES (BM * PITCH)             // 9216
#define B_TILE_BYTES (BN * PITCH)             // 18432
#define STAGE_BYTES (A_TILE_BYTES + B_TILE_BYTES)   // 27648
#define SMEM_BYTES (NS * STAGE_BYTES)               // 110592 -> 2 CTAs/SM

#define REPACK_BLOCKS 11008       // W: 256 thr x 16 int32 each
#define XCVT_BLOCKS   8192        // x: 256 thr x 16 floats each

// ============================================================================
// Device scratch (static globals: allocation-guard safe)
// ============================================================================
__device__ __half g_xh[(size_t)M_TOTAL * K_TOTAL];   // x in fp16
__device__ __half g_wh[(size_t)N_TOTAL * K_TOTAL];   // W in fp16 (exact)

// ============================================================================
// PTX helpers (sm_80-level only: compiles on plain sm_100 target)
// ============================================================================
__device__ __forceinline__ uint32_t smem_u32(const void* p) {
    uint32_t a;
    asm("{ .reg .u64 t; cvta.to.shared.u64 t, %1; cvt.u32.u64 %0, t; }" : "=r"(a) : "l"(p));
    return a;
}

__device__ __forceinline__ void cp_async16(uint32_t saddr, const void* gaddr) {
    asm volatile("cp.async.cg.shared.global [%0], [%1], 16;" :: "r"(saddr), "l"(gaddr));
}
#define CP_COMMIT() asm volatile("cp.async.commit_group;")
#define CP_WAIT(n)  asm volatile("cp.async.wait_group %0;" :: "n"(n))

__device__ __forceinline__ uint32_t lds32(uint32_t a) {
    uint32_t v;
    asm volatile("ld.shared.b32 %0, [%1];" : "=r"(v) : "r"(a));
    return v;
}

__device__ __forceinline__ void mma_f16(float* c, uint32_t a0, uint32_t a1, uint32_t a2,
                                        uint32_t a3, uint32_t b0, uint32_t b1) {
    asm volatile(
        "mma.sync.aligned.m16n8k16.row.col.f32.f16.f16.f32 "
        "{%0,%1,%2,%3}, {%4,%5,%6,%7}, {%8,%9}, {%0,%1,%2,%3};"
        : "+f"(c[0]), "+f"(c[1]), "+f"(c[2]), "+f"(c[3])
        : "r"(a0), "r"(a1), "r"(a2), "r"(a3), "r"(b0), "r"(b1));
}

__device__ __forceinline__ uint32_t pack_half2(__half lo, __half hi) {
    return (uint32_t)__half_as_ushort(lo) | ((uint32_t)__half_as_ushort(hi) << 16);
}

// ============================================================================
// Fused prep: blocks [0, REPACK_BLOCKS) convert W int32 -> fp16 (exact),
// blocks [REPACK_BLOCKS, +XCVT_BLOCKS) convert x fp32 -> fp16 (RN).
// Both branches: per thread 16 source elems -> 16 fp16 -> two uint4 stores.
// ============================================================================
__global__ void __launch_bounds__(256) prep_kernel(const float4* __restrict__ x,
                                                   const int4* __restrict__ w32,
                                                   uint4* __restrict__ wh,
                                                   uint4* __restrict__ xh) {
    const int blk = blockIdx.x;
    const int tid = threadIdx.x;

    if (blk < REPACK_BLOCKS) {
        const uint32_t i = blk * 256 + tid;
        const int4* src = w32 + (size_t)i * 4;
        uint32_t p[8];
#pragma unroll
        for (int j = 0; j < 4; j++) {
            int4 v = src[j];
            p[2 * j]     = pack_half2(__int2half_rn(v.x), __int2half_rn(v.y));
            p[2 * j + 1] = pack_half2(__int2half_rn(v.z), __int2half_rn(v.w));
        }
        wh[2 * i]     = make_uint4(p[0], p[1], p[2], p[3]);
        wh[2 * i + 1] = make_uint4(p[4], p[5], p[6], p[7]);
        return;
    }

    const uint32_t i = (blk - REPACK_BLOCKS) * 256 + tid;
    const float4* src = x + (size_t)i * 4;
    uint32_t p[8];
#pragma unroll
    for (int j = 0; j < 4; j++) {
        float4 v = src[j];
        p[2 * j]     = pack_half2(__float2half_rn(v.x), __float2half_rn(v.y));
        p[2 * j + 1] = pack_half2(__float2half_rn(v.z), __float2half_rn(v.w));
    }
    xh[2 * i]     = make_uint4(p[0], p[1], p[2], p[3]);
    xh[2 * i + 1] = make_uint4(p[4], p[5], p[6], p[7]);
}

// ============================================================================
// GEMM: 256 threads, 8 warps (2m x 4n), warp tile 32x32, fp16 m16n8k16,
// 4-stage cp.async pipeline, 2 CTAs/SM.
// ============================================================================
__global__ void __launch_bounds__(256, 2) gemm_kernel(
    const float* __restrict__ scaler_ptr,
    float* __restrict__ out)
{
    extern __shared__ char dsm[];
    const uint32_t sb = smem_u32(dsm);

    const int tid = threadIdx.x;
    const int wid = tid >> 5;
    const int lane = tid & 31;
    const int g = lane >> 2;        // groupID (0..7)
    const int t = lane & 3;         // thread-in-group (0..3)

    const int warp_m = (wid & 1) * 32;      // 0,32
    const int warp_n = (wid >> 1) * 32;     // 0,32,64,96

    // ---- supertiled rasterization: groups of 8 n-cols, 128 m-tiles fastest ----
    const int b = blockIdx.x;
    const int grp = b >> 10;                // / (8 * GRID_M) = 1024
    const int rem = b & 1023;
    const int gcols = min(8, GRID_N - grp * 8);
    const int nt = grp * 8 + rem % gcols;
    const int mt = rem / gcols;

    const int m0 = mt * BM;
    const int n0 = nt * BN;

    const char* pXA = (const char*)g_xh + (size_t)m0 * K2;
    const char* pWB = (const char*)g_wh + (size_t)n0 * K2;

    // cp.async mapping: rows r=tid>>3 (+32k), 16B chunk q=(tid&7)*16.
    // A: 64 rows x 8 chunks = 512 -> 2/thread. B: 128 x 8 = 1024 -> 4/thread.
    const int rr = tid >> 3;                // 0..31
    const int qq = (tid & 7) * 16;
    const uint32_t sAo = rr * PITCH + qq;
    const size_t gro = (size_t)rr * K2 + qq;

    float acc[2][4][4];
#pragma unroll
    for (int mi = 0; mi < 2; mi++)
#pragma unroll
        for (int ni = 0; ni < 4; ni++)
#pragma unroll
            for (int q = 0; q < 4; q++) acc[mi][ni][q] = 0.0f;

    // ---- prologue: fill stages 0..NS-2 ----
#pragma unroll
    for (int s = 0; s < NS - 1; s++) {
        const int k0b = s * 128;
        const uint32_t so = sb + s * STAGE_BYTES;
        cp_async16(so + sAo,                             pXA + gro + k0b);
        cp_async16(so + 32 * PITCH + sAo,                pXA + gro + (size_t)32 * K2 + k0b);
        cp_async16(so + A_TILE_BYTES + sAo,              pWB + gro + k0b);
        cp_async16(so + A_TILE_BYTES + 32 * PITCH + sAo, pWB + gro + (size_t)32 * K2 + k0b);
        cp_async16(so + A_TILE_BYTES + 64 * PITCH + sAo, pWB + gro + (size_t)64 * K2 + k0b);
        cp_async16(so + A_TILE_BYTES + 96 * PITCH + sAo, pWB + gro + (size_t)96 * K2 + k0b);
        CP_COMMIT();
    }

    for (int kt = 0; kt < KITERS; kt++) {
        CP_WAIT(NS - 2);       // stage kt data complete (this thread's copies)
        __syncthreads();       // stage kt visible to all; stage (kt-1)%NS free

        const int kl = kt + NS - 1;
        if (kl < KITERS) {
            const int k0b = kl * 128;
            const uint32_t so = sb + (kl % NS) * STAGE_BYTES;
            cp_async16(so + sAo,                             pXA + gro + k0b);
            cp_async16(so + 32 * PITCH + sAo,                pXA + gro + (size_t)32 * K2 + k0b);
            cp_async16(so + A_TILE_BYTES + sAo,              pWB + gro + k0b);
            cp_async16(so + A_TILE_BYTES + 32 * PITCH + sAo, pWB + gro + (size_t)32 * K2 + k0b);
            cp_async16(so + A_TILE_BYTES + 64 * PITCH + sAo, pWB + gro + (size_t)64 * K2 + k0b);
            cp_async16(so + A_TILE_BYTES + 96 * PITCH + sAo, pWB + gro + (size_t)96 * K2 + k0b);
        }
        CP_COMMIT();           // uniform group counting even when empty

        const uint32_t sA = sb + (kt % NS) * STAGE_BYTES;
        const uint32_t sB = sA + A_TILE_BYTES;

#pragma unroll
        for (int ks = 0; ks < 4; ks++) {       // k16 elements = 32 bytes each
            const uint32_t kb = ks * 32 + t * 4;
            uint32_t bfr[4][2];
#pragma unroll
            for (int ni = 0; ni < 4; ni++) {
                const uint32_t ad = sB + (uint32_t)(warp_n + ni * 8 + g) * PITCH + kb;
                bfr[ni][0] = lds32(ad);
                bfr[ni][1] = lds32(ad + 16);
            }
#pragma unroll
            for (int mi = 0; mi < 2; mi++) {
                const uint32_t ro = (uint32_t)(warp_m + mi * 16 + g) * PITCH + kb;
                uint32_t a0 = lds32(sA + ro);
                uint32_t a1 = lds32(sA + ro + 8 * PITCH);
                uint32_t a2 = lds32(sA + ro + 16);
                uint32_t a3 = lds32(sA + ro + 8 * PITCH + 16);
#pragma unroll
                for (int ni = 0; ni < 4; ni++)
                    mma_f16(acc[mi][ni], a0, a1, a2, a3, bfr[ni][0], bfr[ni][1]);
            }
        }
    }

    // ---- epilogue: y = scaler * acc ----
    const float sc = *scaler_ptr;
#pragma unroll
    for (int mi = 0; mi < 2; mi++) {
        const int gr0 = m0 + warp_m + mi * 16 + g;
        const int gr1 = gr0 + 8;
        float* o0 = out + (size_t)gr0 * N_TOTAL + n0 + warp_n;
        float* o1 = out + (size_t)gr1 * N_TOTAL + n0 + warp_n;
#pragma unroll
        for (int ni = 0; ni < 4; ni++) {
            const int col = ni * 8 + t * 2;
            float2 y0, y1;
            y0.x = sc * acc[mi][ni][0];
            y0.y = sc * acc[mi][ni][1];
            y1.x = sc * acc[mi][ni][2];
            y1.y = sc * acc[mi][ni][3];
            *reinterpret_cast<float2*>(o0 + col) = y0;
            *reinterpret_cast<float2*>(o1 + col) = y1;
        }
    }
}

// ============================================================================
// Host
// ============================================================================
extern "C" void kernel_launch(void* const* d_in, const int* in_sizes, int n_in,
                              void* d_out, int out_size) {
    const float* x = (const float*)d_in[0];
    const int* w32 = (const int*)d_in[1];     // int8 weights delivered as int32
    const float* scaler = (const float*)d_in[2];
    float* out = (float*)d_out;

    void *p_wh = nullptr, *p_xh = nullptr;
    cudaGetSymbolAddress(&p_wh, g_wh);
    cudaGetSymbolAddress(&p_xh, g_xh);

    prep_kernel<<<REPACK_BLOCKS + XCVT_BLOCKS, 256>>>(
        (const float4*)x, (const int4*)w32, (uint4*)p_wh, (uint4*)p_xh);

    cudaFuncSetAttribute(gemm_kernel, cudaFuncAttributeMaxDynamicSharedMemorySize, SMEM_BYTES);
    gemm_kernel<<<NTILES, 256, SMEM_BYTES>>>(scaler, out);
}

// round 12
// speedup vs baseline: 1.0685x; 1.0685x over previous
#include <cuda_runtime.h>
#include <cuda_bf16.h>
#include <cstdint>

// ============================================================================
// y[M,N] = x[M,K] @ W[N,K]^T * scaler ; x fp32, W int8 (delivered as int32),
// out fp32.
// x -> s1*a + s2*b (two int8 planes, per-row scales); W repacked int32->int8.
// Two int8 mma.sync passes, int32 accumulators, fp32 combine in epilogue.
// Round 12: revert to R8 champion (legacy-IMMA roofline: 1016 MAC/cyc/SM =
// 99% of the half-native-rate ceiling; rt=16/SMSP measured across 4 designs).
// Only change vs R8: prefetch epilogue scales before the mainloop.
// ============================================================================
#define M_TOTAL 8192
#define N_TOTAL 11008
#define K_TOTAL 4096

#define BM 64
#define BN 128
#define BK 64
#define KITERS (K_TOTAL / BK)     // 64
#define GRID_N (N_TOTAL / BN)     // 86
#define GRID_M (M_TOTAL / BM)     // 128
#define NTILES (GRID_N * GRID_M)  // 11008

#define NS 5                       // pipeline stages
#define PITCH 80                   // smem row pitch (bytes): conflict-free quad pattern
#define A_TILE_BYTES (BM * PITCH)  // 5120 per A plane
#define B_TILE_BYTES (BN * PITCH)  // 10240
#define STAGE_BYTES (2 * A_TILE_BYTES + B_TILE_BYTES)   // 20480
#define SMEM_BYTES (NS * STAGE_BYTES)                   // 102400 -> 2 CTAs/SM

#define REPACK_BLOCKS 11008        // 256 thr, 16 int32 each
#define QUANT_BLOCKS  (M_TOTAL / 2) // 256 thr, 2 rows per block

// ============================================================================
// Device scratch (static globals: allocation-guard safe)
// ============================================================================
__device__ int8_t g_qa[(size_t)M_TOTAL * K_TOTAL];   // x hi plane
__device__ int8_t g_qb[(size_t)M_TOTAL * K_TOTAL];   // x lo (residual) plane
__device__ int8_t g_w[(size_t)N_TOTAL * K_TOTAL];    // weights repacked to int8
__device__ float2 g_s[M_TOTAL];                      // {s1, s2} per row

// ============================================================================
// PTX helpers (sm_80-level only: compiles on plain sm_100 target)
// ============================================================================
__device__ __forceinline__ uint32_t smem_u32(const void* p) {
    uint32_t a;
    asm("{ .reg .u64 t; cvta.to.shared.u64 t, %1; cvt.u32.u64 %0, t; }" : "=r"(a) : "l"(p));
    return a;
}

__device__ __forceinline__ void cp_async16(uint32_t saddr, const void* gaddr) {
    asm volatile("cp.async.cg.shared.global [%0], [%1], 16;" :: "r"(saddr), "l"(gaddr));
}
#define CP_COMMIT() asm volatile("cp.async.commit_group;")
#define CP_WAIT(n)  asm volatile("cp.async.wait_group %0;" :: "n"(n))

__device__ __forceinline__ uint32_t lds32(uint32_t a) {
    uint32_t v;
    asm volatile("ld.shared.b32 %0, [%1];" : "=r"(v) : "r"(a));
    return v;
}

__device__ __forceinline__ void mma_s8(int* c, uint32_t a0, uint32_t a1, uint32_t a2, uint32_t a3,
                                       uint32_t b0, uint32_t b1) {
    asm volatile(
        "mma.sync.aligned.m16n8k32.row.col.s32.s8.s8.s32 "
        "{%0,%1,%2,%3}, {%4,%5,%6,%7}, {%8,%9}, {%0,%1,%2,%3};"
        : "+r"(c[0]), "+r"(c[1]), "+r"(c[2]), "+r"(c[3])
        : "r"(a0), "r"(a1), "r"(a2), "r"(a3), "r"(b0), "r"(b1));
}

// ============================================================================
// Fused prep kernel: blocks [0, REPACK_BLOCKS) repack W int32->int8,
// blocks [REPACK_BLOCKS, +QUANT_BLOCKS) quantize x into two int8 planes.
// ============================================================================
__global__ void __launch_bounds__(256) prep_kernel(const float* __restrict__ x,
                                                   const int4* __restrict__ w32,
                                                   uint4* __restrict__ w8) {
    const int blk = blockIdx.x;
    const int tid = threadIdx.x;

    if (blk < REPACK_BLOCKS) {
        const uint32_t i = blk * 256 + tid;
        const int4* src = w32 + (size_t)i * 4;
        uint32_t packed[4];
#pragma unroll
        for (int j = 0; j < 4; j++) {
            int4 v = src[j];
            packed[j] = ((uint32_t)v.x & 0xFFu)
                      | (((uint32_t)v.y & 0xFFu) << 8)
                      | (((uint32_t)v.z & 0xFFu) << 16)
                      | (((uint32_t)v.w & 0xFFu) << 24);
        }
        w8[i] = make_uint4(packed[0], packed[1], packed[2], packed[3]);
        return;
    }

    // ---- quantization: 2 rows per block, 128 threads per row ----
    const int qb = blk - REPACK_BLOCKS;
    const int half = tid >> 7;
    const int tl = tid & 127;
    const int row = qb * 2 + half;
    const int lane = tid & 31;
    const int wid = tid >> 5;

    const float4* xr = reinterpret_cast<const float4*>(x + (size_t)row * K_TOTAL) + tl * 8;
    float4 v[8];
#pragma unroll
    for (int i = 0; i < 8; i++) v[i] = xr[i];

    float am = 0.0f;
#pragma unroll
    for (int i = 0; i < 8; i++) {
        am = fmaxf(am, fabsf(v[i].x)); am = fmaxf(am, fabsf(v[i].y));
        am = fmaxf(am, fabsf(v[i].z)); am = fmaxf(am, fabsf(v[i].w));
    }
#pragma unroll
    for (int off = 16; off > 0; off >>= 1)
        am = fmaxf(am, __shfl_xor_sync(0xFFFFFFFFu, am, off));

    __shared__ float red[8];
    if (lane == 0) red[wid] = am;
    __syncthreads();
    {
        const int base = half * 4;
        am = fmaxf(fmaxf(red[base + 0], red[base + 1]),
                   fmaxf(red[base + 2], red[base + 3]));
    }
    am = fmaxf(am, 1e-20f);

    const float s1 = am * (1.0f / 126.0f);
    const float inv1 = 1.0f / s1;
    const float s2 = s1 * (1.0f / 252.0f);
    const float inv2 = 1.0f / s2;

    uint32_t wa[8], wb[8];
#pragma unroll
    for (int i = 0; i < 8; i++) {
        float f[4] = {v[i].x, v[i].y, v[i].z, v[i].w};
        uint32_t pa = 0, pb = 0;
#pragma unroll
        for (int j = 0; j < 4; j++) {
            int ai = __float2int_rn(f[j] * inv1);
            float r = fmaf(-s1, (float)ai, f[j]);
            int bi = __float2int_rn(r * inv2);
            pa |= ((uint32_t)ai & 0xFFu) << (8 * j);
            pb |= ((uint32_t)bi & 0xFFu) << (8 * j);
        }
        wa[i] = pa; wb[i] = pb;
    }
    uint4* da = reinterpret_cast<uint4*>(g_qa + (size_t)row * K_TOTAL) + tl * 2;
    uint4* db = reinterpret_cast<uint4*>(g_qb + (size_t)row * K_TOTAL) + tl * 2;
    da[0] = make_uint4(wa[0], wa[1], wa[2], wa[3]);
    da[1] = make_uint4(wa[4], wa[5], wa[6], wa[7]);
    db[0] = make_uint4(wb[0], wb[1], wb[2], wb[3]);
    db[1] = make_uint4(wb[4], wb[5], wb[6], wb[7]);
    if (tl == 0) g_s[row] = make_float2(s1, s2);
}

// ============================================================================
// GEMM: 256 threads, 8 warps (2m x 4n), warp tile 32x32, 5-stage pipeline,
// 2 CTAs/SM. Per thread per stage: 4 cp.async (A_hi, A_lo, B row r, B row r+64)
// ============================================================================
__global__ void __launch_bounds__(256, 2) gemm_kernel(
    const float* __restrict__ scaler_ptr,
    float* __restrict__ out)
{
    extern __shared__ char dsm[];
    const uint32_t sb = smem_u32(dsm);

    const int tid = threadIdx.x;
    const int wid = tid >> 5;
    const int lane = tid & 31;
    const int g = lane >> 2;        // groupID (0..7)
    const int t = lane & 3;         // thread-in-group (0..3)

    const int warp_m = (wid & 1) * 32;      // 0,32
    const int warp_n = (wid >> 1) * 32;     // 0,32,64,96

    // ---- supertiled rasterization: groups of 8 n-cols, 128 m-tiles fastest ----
    const int b = blockIdx.x;
    const int grp = b >> 10;                // / (8 * GRID_M) = 1024
    const int rem = b & 1023;
    const int gcols = min(8, GRID_N - grp * 8);
    const int nt = grp * 8 + rem % gcols;
    const int mt = rem / gcols;

    const int m0 = mt * BM;
    const int n0 = nt * BN;

    const int8_t* gAh = g_qa + (size_t)m0 * K_TOTAL;
    const int8_t* gAl = g_qb + (size_t)m0 * K_TOTAL;
    const int8_t* gB  = g_w  + (size_t)n0 * K_TOTAL;

    // ---- prefetch epilogue scales early (hidden behind the K loop) ----
    const int gr0_0 = m0 + warp_m + g;          // mi=0 row pair base
    const int gr0_1 = gr0_0 + 16;               // mi=1 row pair base
    const float2 sv00 = __ldg(&g_s[gr0_0]);
    const float2 sv01 = __ldg(&g_s[gr0_0 + 8]);
    const float2 sv10 = __ldg(&g_s[gr0_1]);
    const float2 sv11 = __ldg(&g_s[gr0_1 + 8]);
    const float sc = __ldg(scaler_ptr);

    // cp.async mapping: A planes: 64 rows x 4 chunks = 256 = one per thread.
    // B: 128 rows x 4 chunks = 512 = two per thread (rows r and r+64).
    const int rr = tid >> 2;                // 0..63
    const int qq = (tid & 3) * 16;
    const uint32_t sA_off = rr * PITCH + qq;
    const uint32_t sB_off2 = sA_off + 64 * PITCH;
    const size_t gA_off = (size_t)rr * K_TOTAL + qq;
    const size_t gB_off2 = gA_off + (size_t)64 * K_TOTAL;

    int accA[2][4][4];
    int accB[2][4][4];
#pragma unroll
    for (int mi = 0; mi < 2; mi++)
#pragma unroll
        for (int ni = 0; ni < 4; ni++)
#pragma unroll
            for (int q = 0; q < 4; q++) { accA[mi][ni][q] = 0; accB[mi][ni][q] = 0; }

    // ---- prologue: fill stages 0..NS-2 ----
#pragma unroll
    for (int s = 0; s < NS - 1; s++) {
        const int k0 = s * BK;
        const uint32_t so = sb + s * STAGE_BYTES;
        cp_async16(so + sA_off,                      gAh + gA_off + k0);
        cp_async16(so + A_TILE_BYTES + sA_off,       gAl + gA_off + k0);
        cp_async16(so + 2 * A_TILE_BYTES + sA_off,   gB  + gA_off + k0);
        cp_async16(so + 2 * A_TILE_BYTES + sB_off2,  gB  + gB_off2 + k0);
        CP_COMMIT();
    }

    for (int kt = 0; kt < KITERS; kt++) {
        CP_WAIT(NS - 2);       // stage kt data complete (this thread's copies)
        __syncthreads();       // stage kt visible to all; stage (kt-1)%NS free

        const int kl = kt + NS - 1;
        if (kl < KITERS) {
            const int k0 = kl * BK;
            const uint32_t so = sb + (kl % NS) * STAGE_BYTES;
            cp_async16(so + sA_off,                      gAh + gA_off + k0);
            cp_async16(so + A_TILE_BYTES + sA_off,       gAl + gA_off + k0);
            cp_async16(so + 2 * A_TILE_BYTES + sA_off,   gB  + gA_off + k0);
            cp_async16(so + 2 * A_TILE_BYTES + sB_off2,  gB  + gB_off2 + k0);
        }
        CP_COMMIT();           // uniform group counting even when empty

        const uint32_t sA  = sb + (kt % NS) * STAGE_BYTES;
        const uint32_t sAl = sA + A_TILE_BYTES;
        const uint32_t sB  = sA + 2 * A_TILE_BYTES;

#pragma unroll
        for (int ks = 0; ks < 2; ks++) {
            const uint32_t kb = ks * 32 + t * 4;
            uint32_t bfr[4][2];
#pragma unroll
            for (int ni = 0; ni < 4; ni++) {
                const uint32_t ad = sB + (uint32_t)(warp_n + ni * 8 + g) * PITCH + kb;
                bfr[ni][0] = lds32(ad);
                bfr[ni][1] = lds32(ad + 16);
            }
#pragma unroll
            for (int mi = 0; mi < 2; mi++) {
                const uint32_t ro = (uint32_t)(warp_m + mi * 16 + g) * PITCH + kb;
                uint32_t a0 = lds32(sA + ro);
                uint32_t a1 = lds32(sA + ro + 8 * PITCH);
                uint32_t a2 = lds32(sA + ro + 16);
                uint32_t a3 = lds32(sA + ro + 8 * PITCH + 16);
#pragma unroll
                for (int ni = 0; ni < 4; ni++)
                    mma_s8(accA[mi][ni], a0, a1, a2, a3, bfr[ni][0], bfr[ni][1]);
                uint32_t l0 = lds32(sAl + ro);
                uint32_t l1 = lds32(sAl + ro + 8 * PITCH);
                uint32_t l2 = lds32(sAl + ro + 16);
                uint32_t l3 = lds32(sAl + ro + 8 * PITCH + 16);
#pragma unroll
                for (int ni = 0; ni < 4; ni++)
                    mma_s8(accB[mi][ni], l0, l1, l2, l3, bfr[ni][0], bfr[ni][1]);
            }
        }
    }

    // ---- epilogue ----
#pragma unroll
    for (int mi = 0; mi < 2; mi++) {
        const int gr0 = m0 + warp_m + mi * 16 + g;
        const int gr1 = gr0 + 8;
        const float2 sv0 = mi ? sv10 : sv00;
        const float2 sv1 = mi ? sv11 : sv01;
        const float f1a = sc * sv0.x, f2a = sc * sv0.y;
        const float f1b = sc * sv1.x, f2b = sc * sv1.y;
        float* o0 = out + (size_t)gr0 * N_TOTAL + n0 + warp_n;
        float* o1 = out + (size_t)gr1 * N_TOTAL + n0 + warp_n;
#pragma unroll
        for (int ni = 0; ni < 4; ni++) {
            const int col = ni * 8 + t * 2;
            float2 y0, y1;
            y0.x = f1a * (float)accA[mi][ni][0] + f2a * (float)accB[mi][ni][0];
            y0.y = f1a * (float)accA[mi][ni][1] + f2a * (float)accB[mi][ni][1];
            y1.x = f1b * (float)accA[mi][ni][2] + f2b * (float)accB[mi][ni][2];
            y1.y = f1b * (float)accA[mi][ni][3] + f2b * (float)accB[mi][ni][3];
            *reinterpret_cast<float2*>(o0 + col) = y0;
            *reinterpret_cast<float2*>(o1 + col) = y1;
        }
    }
}

// ============================================================================
// Host
// ============================================================================
extern "C" void kernel_launch(void* const* d_in, const int* in_sizes, int n_in,
                              void* d_out, int out_size) {
    const float* x = (const float*)d_in[0];
    const int* w32 = (const int*)d_in[1];     // int8 weights delivered as int32
    const float* scaler = (const float*)d_in[2];
    float* out = (float*)d_out;

    void* p_w = nullptr;
    cudaGetSymbolAddress(&p_w, g_w);

    prep_kernel<<<REPACK_BLOCKS + QUANT_BLOCKS, 256>>>(x, (const int4*)w32, (uint4*)p_w);

    cudaFuncSetAttribute(gemm_kernel, cudaFuncAttributeMaxDynamicSharedMemorySize, SMEM_BYTES);
    gemm_kernel<<<NTILES, 256, SMEM_BYTES>>>(scaler, out);
}

// round 13
// speedup vs baseline: 1.1456x; 1.0721x over previous
#include <cuda_runtime.h>
#include <cuda_bf16.h>
#include <cstdint>

// ============================================================================
// y[M,N] = x[M,K] @ W[N,K]^T * scaler ; x fp32, W int8 (delivered as int32),
// out fp32.
// x -> s1*a + s2*b (two int8 planes, per-row scales); W repacked int32->int8.
// Two int8 mma.sync passes, int32 accumulators, fp32 combine in epilogue.
// FINAL (= Round 8 champion, byte-identical): 256-thread CTAs (BM=64 x
// BN=128), 2 CTAs/SM, 5-stage cp.async pipeline. GEMM measured at ~100% of
// the legacy-IMMA ceiling (1024 MAC/cyc/SM, rt=16/SMSP); scale loads stay in
// the epilogue (hoisting them measurably regressed the mainloop schedule).
// ============================================================================
#define M_TOTAL 8192
#define N_TOTAL 11008
#define K_TOTAL 4096

#define BM 64
#define BN 128
#define BK 64
#define KITERS (K_TOTAL / BK)     // 64
#define GRID_N (N_TOTAL / BN)     // 86
#define GRID_M (M_TOTAL / BM)     // 128
#define NTILES (GRID_N * GRID_M)  // 11008

#define NS 5                       // pipeline stages
#define PITCH 80                   // smem row pitch (bytes): conflict-free quad pattern
#define A_TILE_BYTES (BM * PITCH)  // 5120 per A plane
#define B_TILE_BYTES (BN * PITCH)  // 10240
#define STAGE_BYTES (2 * A_TILE_BYTES + B_TILE_BYTES)   // 20480
#define SMEM_BYTES (NS * STAGE_BYTES)                   // 102400 -> 2 CTAs/SM

#define REPACK_BLOCKS 11008        // 256 thr, 16 int32 each
#define QUANT_BLOCKS  (M_TOTAL / 2) // 256 thr, 2 rows per block

// ============================================================================
// Device scratch (static globals: allocation-guard safe)
// ============================================================================
__device__ int8_t g_qa[(size_t)M_TOTAL * K_TOTAL];   // x hi plane
__device__ int8_t g_qb[(size_t)M_TOTAL * K_TOTAL];   // x lo (residual) plane
__device__ int8_t g_w[(size_t)N_TOTAL * K_TOTAL];    // weights repacked to int8
__device__ float2 g_s[M_TOTAL];                      // {s1, s2} per row

// ============================================================================
// PTX helpers (sm_80-level only: compiles on plain sm_100 target)
// ============================================================================
__device__ __forceinline__ uint32_t smem_u32(const void* p) {
    uint32_t a;
    asm("{ .reg .u64 t; cvta.to.shared.u64 t, %1; cvt.u32.u64 %0, t; }" : "=r"(a) : "l"(p));
    return a;
}

__device__ __forceinline__ void cp_async16(uint32_t saddr, const void* gaddr) {
    asm volatile("cp.async.cg.shared.global [%0], [%1], 16;" :: "r"(saddr), "l"(gaddr));
}
#define CP_COMMIT() asm volatile("cp.async.commit_group;")
#define CP_WAIT(n)  asm volatile("cp.async.wait_group %0;" :: "n"(n))

__device__ __forceinline__ uint32_t lds32(uint32_t a) {
    uint32_t v;
    asm volatile("ld.shared.b32 %0, [%1];" : "=r"(v) : "r"(a));
    return v;
}

__device__ __forceinline__ void mma_s8(int* c, uint32_t a0, uint32_t a1, uint32_t a2, uint32_t a3,
                                       uint32_t b0, uint32_t b1) {
    asm volatile(
        "mma.sync.aligned.m16n8k32.row.col.s32.s8.s8.s32 "
        "{%0,%1,%2,%3}, {%4,%5,%6,%7}, {%8,%9}, {%0,%1,%2,%3};"
        : "+r"(c[0]), "+r"(c[1]), "+r"(c[2]), "+r"(c[3])
        : "r"(a0), "r"(a1), "r"(a2), "r"(a3), "r"(b0), "r"(b1));
}

// ============================================================================
// Fused prep kernel: blocks [0, REPACK_BLOCKS) repack W int32->int8,
// blocks [REPACK_BLOCKS, +QUANT_BLOCKS) quantize x into two int8 planes.
// ============================================================================
__global__ void __launch_bounds__(256) prep_kernel(const float* __restrict__ x,
                                                   const int4* __restrict__ w32,
                                                   uint4* __restrict__ w8) {
    const int blk = blockIdx.x;
    const int tid = threadIdx.x;

    if (blk < REPACK_BLOCKS) {
        const uint32_t i = blk * 256 + tid;
        const int4* src = w32 + (size_t)i * 4;
        uint32_t packed[4];
#pragma unroll
        for (int j = 0; j < 4; j++) {
            int4 v = src[j];
            packed[j] = ((uint32_t)v.x & 0xFFu)
                      | (((uint32_t)v.y & 0xFFu) << 8)
                      | (((uint32_t)v.z & 0xFFu) << 16)
                      | (((uint32_t)v.w & 0xFFu) << 24);
        }
        w8[i] = make_uint4(packed[0], packed[1], packed[2], packed[3]);
        return;
    }

    // ---- quantization: 2 rows per block, 128 threads per row ----
    const int qb = blk - REPACK_BLOCKS;
    const int half = tid >> 7;
    const int tl = tid & 127;
    const int row = qb * 2 + half;
    const int lane = tid & 31;
    const int wid = tid >> 5;

    const float4* xr = reinterpret_cast<const float4*>(x + (size_t)row * K_TOTAL) + tl * 8;
    float4 v[8];
#pragma unroll
    for (int i = 0; i < 8; i++) v[i] = xr[i];

    float am = 0.0f;
#pragma unroll
    for (int i = 0; i < 8; i++) {
        am = fmaxf(am, fabsf(v[i].x)); am = fmaxf(am, fabsf(v[i].y));
        am = fmaxf(am, fabsf(v[i].z)); am = fmaxf(am, fabsf(v[i].w));
    }
#pragma unroll
    for (int off = 16; off > 0; off >>= 1)
        am = fmaxf(am, __shfl_xor_sync(0xFFFFFFFFu, am, off));

    __shared__ float red[8];
    if (lane == 0) red[wid] = am;
    __syncthreads();
    {
        const int base = half * 4;
        am = fmaxf(fmaxf(red[base + 0], red[base + 1]),
                   fmaxf(red[base + 2], red[base + 3]));
    }
    am = fmaxf(am, 1e-20f);

    const float s1 = am * (1.0f / 126.0f);
    const float inv1 = 1.0f / s1;
    const float s2 = s1 * (1.0f / 252.0f);
    const float inv2 = 1.0f / s2;

    uint32_t wa[8], wb[8];
#pragma unroll
    for (int i = 0; i < 8; i++) {
        float f[4] = {v[i].x, v[i].y, v[i].z, v[i].w};
        uint32_t pa = 0, pb = 0;
#pragma unroll
        for (int j = 0; j < 4; j++) {
            int ai = __float2int_rn(f[j] * inv1);
            float r = fmaf(-s1, (float)ai, f[j]);
            int bi = __float2int_rn(r * inv2);
            pa |= ((uint32_t)ai & 0xFFu) << (8 * j);
            pb |= ((uint32_t)bi & 0xFFu) << (8 * j);
        }
        wa[i] = pa; wb[i] = pb;
    }
    uint4* da = reinterpret_cast<uint4*>(g_qa + (size_t)row * K_TOTAL) + tl * 2;
    uint4* db = reinterpret_cast<uint4*>(g_qb + (size_t)row * K_TOTAL) + tl * 2;
    da[0] = make_uint4(wa[0], wa[1], wa[2], wa[3]);
    da[1] = make_uint4(wa[4], wa[5], wa[6], wa[7]);
    db[0] = make_uint4(wb[0], wb[1], wb[2], wb[3]);
    db[1] = make_uint4(wb[4], wb[5], wb[6], wb[7]);
    if (tl == 0) g_s[row] = make_float2(s1, s2);
}

// ============================================================================
// GEMM: 256 threads, 8 warps (2m x 4n), warp tile 32x32, 5-stage pipeline,
// 2 CTAs/SM. Per thread per stage: 4 cp.async (A_hi, A_lo, B row r, B row r+64)
// ============================================================================
__global__ void __launch_bounds__(256, 2) gemm_kernel(
    const float* __restrict__ scaler_ptr,
    float* __restrict__ out)
{
    extern __shared__ char dsm[];
    const uint32_t sb = smem_u32(dsm);

    const int tid = threadIdx.x;
    const int wid = tid >> 5;
    const int lane = tid & 31;
    const int g = lane >> 2;        // groupID (0..7)
    const int t = lane & 3;         // thread-in-group (0..3)

    const int warp_m = (wid & 1) * 32;      // 0,32
    const int warp_n = (wid >> 1) * 32;     // 0,32,64,96

    // ---- supertiled rasterization: groups of 8 n-cols, 128 m-tiles fastest ----
    const int b = blockIdx.x;
    const int grp = b >> 10;                // / (8 * GRID_M) = 1024
    const int rem = b & 1023;
    const int gcols = min(8, GRID_N - grp * 8);
    const int nt = grp * 8 + rem % gcols;
    const int mt = rem / gcols;

    const int m0 = mt * BM;
    const int n0 = nt * BN;

    const int8_t* gAh = g_qa + (size_t)m0 * K_TOTAL;
    const int8_t* gAl = g_qb + (size_t)m0 * K_TOTAL;
    const int8_t* gB  = g_w  + (size_t)n0 * K_TOTAL;

    // cp.async mapping: A planes: 64 rows x 4 chunks = 256 = one per thread.
    // B: 128 rows x 4 chunks = 512 = two per thread (rows r and r+64).
    const int rr = tid >> 2;                // 0..63
    const int qq = (tid & 3) * 16;
    const uint32_t sA_off = rr * PITCH + qq;
    const uint32_t sB_off2 = sA_off + 64 * PITCH;
    const size_t gA_off = (size_t)rr * K_TOTAL + qq;
    const size_t gB_off2 = gA_off + (size_t)64 * K_TOTAL;

    int accA[2][4][4];
    int accB[2][4][4];
#pragma unroll
    for (int mi = 0; mi < 2; mi++)
#pragma unroll
        for (int ni = 0; ni < 4; ni++)
#pragma unroll
            for (int q = 0; q < 4; q++) { accA[mi][ni][q] = 0; accB[mi][ni][q] = 0; }

    // ---- prologue: fill stages 0..NS-2 ----
#pragma unroll
    for (int s = 0; s < NS - 1; s++) {
        const int k0 = s * BK;
        const uint32_t so = sb + s * STAGE_BYTES;
        cp_async16(so + sA_off,                      gAh + gA_off + k0);
        cp_async16(so + A_TILE_BYTES + sA_off,       gAl + gA_off + k0);
        cp_async16(so + 2 * A_TILE_BYTES + sA_off,   gB  + gA_off + k0);
        cp_async16(so + 2 * A_TILE_BYTES + sB_off2,  gB  + gB_off2 + k0);
        CP_COMMIT();
    }

    for (int kt = 0; kt < KITERS; kt++) {
        CP_WAIT(NS - 2);       // stage kt data complete (this thread's copies)
        __syncthreads();       // stage kt visible to all; stage (kt-1)%NS free

        const int kl = kt + NS - 1;
        if (kl < KITERS) {
            const int k0 = kl * BK;
            const uint32_t so = sb + (kl % NS) * STAGE_BYTES;
            cp_async16(so + sA_off,                      gAh + gA_off + k0);
            cp_async16(so + A_TILE_BYTES + sA_off,       gAl + gA_off + k0);
            cp_async16(so + 2 * A_TILE_BYTES + sA_off,   gB  + gA_off + k0);
            cp_async16(so + 2 * A_TILE_BYTES + sB_off2,  gB  + gB_off2 + k0);
        }
        CP_COMMIT();           // uniform group counting even when empty

        const uint32_t sA  = sb + (kt % NS) * STAGE_BYTES;
        const uint32_t sAl = sA + A_TILE_BYTES;
        const uint32_t sB  = sA + 2 * A_TILE_BYTES;

#pragma unroll
        for (int ks = 0; ks < 2; ks++) {
            const uint32_t kb = ks * 32 + t * 4;
            uint32_t bfr[4][2];
#pragma unroll
            for (int ni = 0; ni < 4; ni++) {
                const uint32_t ad = sB + (uint32_t)(warp_n + ni * 8 + g) * PITCH + kb;
                bfr[ni][0] = lds32(ad);
                bfr[ni][1] = lds32(ad + 16);
            }
#pragma unroll
            for (int mi = 0; mi < 2; mi++) {
                const uint32_t ro = (uint32_t)(warp_m + mi * 16 + g) * PITCH + kb;
                uint32_t a0 = lds32(sA + ro);
                uint32_t a1 = lds32(sA + ro + 8 * PITCH);
                uint32_t a2 = lds32(sA + ro + 16);
                uint32_t a3 = lds32(sA + ro + 8 * PITCH + 16);
#pragma unroll
                for (int ni = 0; ni < 4; ni++)
                    mma_s8(accA[mi][ni], a0, a1, a2, a3, bfr[ni][0], bfr[ni][1]);
                uint32_t l0 = lds32(sAl + ro);
                uint32_t l1 = lds32(sAl + ro + 8 * PITCH);
                uint32_t l2 = lds32(sAl + ro + 16);
                uint32_t l3 = lds32(sAl + ro + 8 * PITCH + 16);
#pragma unroll
                for (int ni = 0; ni < 4; ni++)
                    mma_s8(accB[mi][ni], l0, l1, l2, l3, bfr[ni][0], bfr[ni][1]);
            }
        }
    }

    // ---- epilogue ----
    const float sc = *scaler_ptr;
#pragma unroll
    for (int mi = 0; mi < 2; mi++) {
        const int gr0 = m0 + warp_m + mi * 16 + g;
        const int gr1 = gr0 + 8;
        const float2 sv0 = __ldg(&g_s[gr0]);
        const float2 sv1 = __ldg(&g_s[gr1]);
        const float f1a = sc * sv0.x, f2a = sc * sv0.y;
        const float f1b = sc * sv1.x, f2b = sc * sv1.y;
        float* o0 = out + (size_t)gr0 * N_TOTAL + n0 + warp_n;
        float* o1 = out + (size_t)gr1 * N_TOTAL + n0 + warp_n;
#pragma unroll
        for (int ni = 0; ni < 4; ni++) {
            const int col = ni * 8 + t * 2;
            float2 y0, y1;
            y0.x = f1a * (float)accA[mi][ni][0] + f2a * (float)accB[mi][ni][0];
            y0.y = f1a * (float)accA[mi][ni][1] + f2a * (float)accB[mi][ni][1];
            y1.x = f1b * (float)accA[mi][ni][2] + f2b * (float)accB[mi][ni][2];
            y1.y = f1b * (float)accA[mi][ni][3] + f2b * (float)accB[mi][ni][3];
            *reinterpret_cast<float2*>(o0 + col) = y0;
            *reinterpret_cast<float2*>(o1 + col) = y1;
        }
    }
}

// ============================================================================
// Host
// ============================================================================
extern "C" void kernel_launch(void* const* d_in, const int* in_sizes, int n_in,
                              void* d_out, int out_size) {
    const float* x = (const float*)d_in[0];
    const int* w32 = (const int*)d_in[1];     // int8 weights delivered as int32
    const float* scaler = (const float*)d_in[2];
    float* out = (float*)d_out;

    void* p_w = nullptr;
    cudaGetSymbolAddress(&p_w, g_w);

    prep_kernel<<<REPACK_BLOCKS + QUANT_BLOCKS, 256>>>(x, (const int4*)w32, (uint4*)p_w);

    cudaFuncSetAttribute(gemm_kernel, cudaFuncAttributeMaxDynamicSharedMemorySize, SMEM_BYTES);
    gemm_kernel<<<NTILES, 256, SMEM_BYTES>>>(scaler, out);
}

// round 14
// speedup vs baseline: 1.1513x; 1.0050x over previous
#include <cuda_runtime.h>
#include <cuda_bf16.h>
#include <cstdint>

// ============================================================================
// y[M,N] = x[M,K] @ W[N,K]^T * scaler ; x fp32, W int8 (delivered as int32),
// out fp32.
// x -> s1*a + s2*b (two int8 planes, per-row scales); W repacked int32->int8.
// Two int8 mma.sync passes, int32 accumulators, fp32 combine in epilogue.
// FINAL champion (Round 8 configuration, re-confirmed Round 13):
//   - 256-thread CTAs (BM=64 x BN=128), 2 CTAs/SM, 5-stage cp.async pipeline
//   - GEMM at ~100% of the legacy-IMMA ceiling (1024 MAC/cyc/SM, rt=16/SMSP;
//     ncu tensor% reads ~52 because its peak is the 2x native tcgen05 rate,
//     which plain-sm_100 ptxas cannot target: no tcgen05.ld readback)
//   - instruction count (1.8e8 s8-mma) minimal for rel_err < 1e-3 on this ISA
//   - measured deviations (ldmatrix, fp16, scale-prefetch) all regressed
// ============================================================================
#define M_TOTAL 8192
#define N_TOTAL 11008
#define K_TOTAL 4096

#define BM 64
#define BN 128
#define BK 64
#define KITERS (K_TOTAL / BK)     // 64
#define GRID_N (N_TOTAL / BN)     // 86
#define GRID_M (M_TOTAL / BM)     // 128
#define NTILES (GRID_N * GRID_M)  // 11008

#define NS 5                       // pipeline stages
#define PITCH 80                   // smem row pitch (bytes): conflict-free quad pattern
#define A_TILE_BYTES (BM * PITCH)  // 5120 per A plane
#define B_TILE_BYTES (BN * PITCH)  // 10240
#define STAGE_BYTES (2 * A_TILE_BYTES + B_TILE_BYTES)   // 20480
#define SMEM_BYTES (NS * STAGE_BYTES)                   // 102400 -> 2 CTAs/SM

#define REPACK_BLOCKS 11008        // 256 thr, 16 int32 each
#define QUANT_BLOCKS  (M_TOTAL / 2) // 256 thr, 2 rows per block

// ============================================================================
// Device scratch (static globals: allocation-guard safe)
// ============================================================================
__device__ int8_t g_qa[(size_t)M_TOTAL * K_TOTAL];   // x hi plane
__device__ int8_t g_qb[(size_t)M_TOTAL * K_TOTAL];   // x lo (residual) plane
__device__ int8_t g_w[(size_t)N_TOTAL * K_TOTAL];    // weights repacked to int8
__device__ float2 g_s[M_TOTAL];                      // {s1, s2} per row

// ============================================================================
// PTX helpers (sm_80-level only: compiles on plain sm_100 target)
// ============================================================================
__device__ __forceinline__ uint32_t smem_u32(const void* p) {
    uint32_t a;
    asm("{ .reg .u64 t; cvta.to.shared.u64 t, %1; cvt.u32.u64 %0, t; }" : "=r"(a) : "l"(p));
    return a;
}

__device__ __forceinline__ void cp_async16(uint32_t saddr, const void* gaddr) {
    asm volatile("cp.async.cg.shared.global [%0], [%1], 16;" :: "r"(saddr), "l"(gaddr));
}
#define CP_COMMIT() asm volatile("cp.async.commit_group;")
#define CP_WAIT(n)  asm volatile("cp.async.wait_group %0;" :: "n"(n))

__device__ __forceinline__ uint32_t lds32(uint32_t a) {
    uint32_t v;
    asm volatile("ld.shared.b32 %0, [%1];" : "=r"(v) : "r"(a));
    return v;
}

__device__ __forceinline__ void mma_s8(int* c, uint32_t a0, uint32_t a1, uint32_t a2, uint32_t a3,
                                       uint32_t b0, uint32_t b1) {
    asm volatile(
        "mma.sync.aligned.m16n8k32.row.col.s32.s8.s8.s32 "
        "{%0,%1,%2,%3}, {%4,%5,%6,%7}, {%8,%9}, {%0,%1,%2,%3};"
        : "+r"(c[0]), "+r"(c[1]), "+r"(c[2]), "+r"(c[3])
        : "r"(a0), "r"(a1), "r"(a2), "r"(a3), "r"(b0), "r"(b1));
}

// ============================================================================
// Fused prep kernel: blocks [0, REPACK_BLOCKS) repack W int32->int8,
// blocks [REPACK_BLOCKS, +QUANT_BLOCKS) quantize x into two int8 planes.
// ============================================================================
__global__ void __launch_bounds__(256) prep_kernel(const float* __restrict__ x,
                                                   const int4* __restrict__ w32,
                                                   uint4* __restrict__ w8) {
    const int blk = blockIdx.x;
    const int tid = threadIdx.x;

    if (blk < REPACK_BLOCKS) {
        const uint32_t i = blk * 256 + tid;
        const int4* src = w32 + (size_t)i * 4;
        uint32_t packed[4];
#pragma unroll
        for (int j = 0; j < 4; j++) {
            int4 v = src[j];
            packed[j] = ((uint32_t)v.x & 0xFFu)
                      | (((uint32_t)v.y & 0xFFu) << 8)
                      | (((uint32_t)v.z & 0xFFu) << 16)
                      | (((uint32_t)v.w & 0xFFu) << 24);
        }
        w8[i] = make_uint4(packed[0], packed[1], packed[2], packed[3]);
        return;
    }

    // ---- quantization: 2 rows per block, 128 threads per row ----
    const int qb = blk - REPACK_BLOCKS;
    const int half = tid >> 7;
    const int tl = tid & 127;
    const int row = qb * 2 + half;
    const int lane = tid & 31;
    const int wid = tid >> 5;

    const float4* xr = reinterpret_cast<const float4*>(x + (size_t)row * K_TOTAL) + tl * 8;
    float4 v[8];
#pragma unroll
    for (int i = 0; i < 8; i++) v[i] = xr[i];

    float am = 0.0f;
#pragma unroll
    for (int i = 0; i < 8; i++) {
        am = fmaxf(am, fabsf(v[i].x)); am = fmaxf(am, fabsf(v[i].y));
        am = fmaxf(am, fabsf(v[i].z)); am = fmaxf(am, fabsf(v[i].w));
    }
#pragma unroll
    for (int off = 16; off > 0; off >>= 1)
        am = fmaxf(am, __shfl_xor_sync(0xFFFFFFFFu, am, off));

    __shared__ float red[8];
    if (lane == 0) red[wid] = am;
    __syncthreads();
    {
        const int base = half * 4;
        am = fmaxf(fmaxf(red[base + 0], red[base + 1]),
                   fmaxf(red[base + 2], red[base + 3]));
    }
    am = fmaxf(am, 1e-20f);

    const float s1 = am * (1.0f / 126.0f);
    const float inv1 = 1.0f / s1;
    const float s2 = s1 * (1.0f / 252.0f);
    const float inv2 = 1.0f / s2;

    uint32_t wa[8], wb[8];
#pragma unroll
    for (int i = 0; i < 8; i++) {
        float f[4] = {v[i].x, v[i].y, v[i].z, v[i].w};
        uint32_t pa = 0, pb = 0;
#pragma unroll
        for (int j = 0; j < 4; j++) {
            int ai = __float2int_rn(f[j] * inv1);
            float r = fmaf(-s1, (float)ai, f[j]);
            int bi = __float2int_rn(r * inv2);
            pa |= ((uint32_t)ai & 0xFFu) << (8 * j);
            pb |= ((uint32_t)bi & 0xFFu) << (8 * j);
        }
        wa[i] = pa; wb[i] = pb;
    }
    uint4* da = reinterpret_cast<uint4*>(g_qa + (size_t)row * K_TOTAL) + tl * 2;
    uint4* db = reinterpret_cast<uint4*>(g_qb + (size_t)row * K_TOTAL) + tl * 2;
    da[0] = make_uint4(wa[0], wa[1], wa[2], wa[3]);
    da[1] = make_uint4(wa[4], wa[5], wa[6], wa[7]);
    db[0] = make_uint4(wb[0], wb[1], wb[2], wb[3]);
    db[1] = make_uint4(wb[4], wb[5], wb[6], wb[7]);
    if (tl == 0) g_s[row] = make_float2(s1, s2);
}

// ============================================================================
// GEMM: 256 threads, 8 warps (2m x 4n), warp tile 32x32, 5-stage pipeline,
// 2 CTAs/SM. Per thread per stage: 4 cp.async (A_hi, A_lo, B row r, B row r+64)
// ============================================================================
__global__ void __launch_bounds__(256, 2) gemm_kernel(
    const float* __restrict__ scaler_ptr,
    float* __restrict__ out)
{
    extern __shared__ char dsm[];
    const uint32_t sb = smem_u32(dsm);

    const int tid = threadIdx.x;
    const int wid = tid >> 5;
    const int lane = tid & 31;
    const int g = lane >> 2;        // groupID (0..7)
    const int t = lane & 3;         // thread-in-group (0..3)

    const int warp_m = (wid & 1) * 32;      // 0,32
    const int warp_n = (wid >> 1) * 32;     // 0,32,64,96

    // ---- supertiled rasterization: groups of 8 n-cols, 128 m-tiles fastest ----
    const int b = blockIdx.x;
    const int grp = b >> 10;                // / (8 * GRID_M) = 1024
    const int rem = b & 1023;
    const int gcols = min(8, GRID_N - grp * 8);
    const int nt = grp * 8 + rem % gcols;
    const int mt = rem / gcols;

    const int m0 = mt * BM;
    const int n0 = nt * BN;

    const int8_t* gAh = g_qa + (size_t)m0 * K_TOTAL;
    const int8_t* gAl = g_qb + (size_t)m0 * K_TOTAL;
    const int8_t* gB  = g_w  + (size_t)n0 * K_TOTAL;

    // cp.async mapping: A planes: 64 rows x 4 chunks = 256 = one per thread.
    // B: 128 rows x 4 chunks = 512 = two per thread (rows r and r+64).
    const int rr = tid >> 2;                // 0..63
    const int qq = (tid & 3) * 16;
    const uint32_t sA_off = rr * PITCH + qq;
    const uint32_t sB_off2 = sA_off + 64 * PITCH;
    const size_t gA_off = (size_t)rr * K_TOTAL + qq;
    const size_t gB_off2 = gA_off + (size_t)64 * K_TOTAL;

    int accA[2][4][4];
    int accB[2][4][4];
#pragma unroll
    for (int mi = 0; mi < 2; mi++)
#pragma unroll
        for (int ni = 0; ni < 4; ni++)
#pragma unroll
            for (int q = 0; q < 4; q++) { accA[mi][ni][q] = 0; accB[mi][ni][q] = 0; }

    // ---- prologue: fill stages 0..NS-2 ----
#pragma unroll
    for (int s = 0; s < NS - 1; s++) {
        const int k0 = s * BK;
        const uint32_t so = sb + s * STAGE_BYTES;
        cp_async16(so + sA_off,                      gAh + gA_off + k0);
        cp_async16(so + A_TILE_BYTES + sA_off,       gAl + gA_off + k0);
        cp_async16(so + 2 * A_TILE_BYTES + sA_off,   gB  + gA_off + k0);
        cp_async16(so + 2 * A_TILE_BYTES + sB_off2,  gB  + gB_off2 + k0);
        CP_COMMIT();
    }

    for (int kt = 0; kt < KITERS; kt++) {
        CP_WAIT(NS - 2);       // stage kt data complete (this thread's copies)
        __syncthreads();       // stage kt visible to all; stage (kt-1)%NS free

        const int kl = kt + NS - 1;
        if (kl < KITERS) {
            const int k0 = kl * BK;
            const uint32_t so = sb + (kl % NS) * STAGE_BYTES;
            cp_async16(so + sA_off,                      gAh + gA_off + k0);
            cp_async16(so + A_TILE_BYTES + sA_off,       gAl + gA_off + k0);
            cp_async16(so + 2 * A_TILE_BYTES + sA_off,   gB  + gA_off + k0);
            cp_async16(so + 2 * A_TILE_BYTES + sB_off2,  gB  + gB_off2 + k0);
        }
        CP_COMMIT();           // uniform group counting even when empty

        const uint32_t sA  = sb + (kt % NS) * STAGE_BYTES;
        const uint32_t sAl = sA + A_TILE_BYTES;
        const uint32_t sB  = sA + 2 * A_TILE_BYTES;

#pragma unroll
        for (int ks = 0; ks < 2; ks++) {
            const uint32_t kb = ks * 32 + t * 4;
            uint32_t bfr[4][2];
#pragma unroll
            for (int ni = 0; ni < 4; ni++) {
                const uint32_t ad = sB + (uint32_t)(warp_n + ni * 8 + g) * PITCH + kb;
                bfr[ni][0] = lds32(ad);
                bfr[ni][1] = lds32(ad + 16);
            }
#pragma unroll
            for (int mi = 0; mi < 2; mi++) {
                const uint32_t ro = (uint32_t)(warp_m + mi * 16 + g) * PITCH + kb;
                uint32_t a0 = lds32(sA + ro);
                uint32_t a1 = lds32(sA + ro + 8 * PITCH);
                uint32_t a2 = lds32(sA + ro + 16);
                uint32_t a3 = lds32(sA + ro + 8 * PITCH + 16);
#pragma unroll
                for (int ni = 0; ni < 4; ni++)
                    mma_s8(accA[mi][ni], a0, a1, a2, a3, bfr[ni][0], bfr[ni][1]);
                uint32_t l0 = lds32(sAl + ro);
                uint32_t l1 = lds32(sAl + ro + 8 * PITCH);
                uint32_t l2 = lds32(sAl + ro + 16);
                uint32_t l3 = lds32(sAl + ro + 8 * PITCH + 16);
#pragma unroll
                for (int ni = 0; ni < 4; ni++)
                    mma_s8(accB[mi][ni], l0, l1, l2, l3, bfr[ni][0], bfr[ni][1]);
            }
        }
    }

    // ---- epilogue ----
    const float sc = *scaler_ptr;
#pragma unroll
    for (int mi = 0; mi < 2; mi++) {
        const int gr0 = m0 + warp_m + mi * 16 + g;
        const int gr1 = gr0 + 8;
        const float2 sv0 = __ldg(&g_s[gr0]);
        const float2 sv1 = __ldg(&g_s[gr1]);
        const float f1a = sc * sv0.x, f2a = sc * sv0.y;
        const float f1b = sc * sv1.x, f2b = sc * sv1.y;
        float* o0 = out + (size_t)gr0 * N_TOTAL + n0 + warp_n;
        float* o1 = out + (size_t)gr1 * N_TOTAL + n0 + warp_n;
#pragma unroll
        for (int ni = 0; ni < 4; ni++) {
            const int col = ni * 8 + t * 2;
            float2 y0, y1;
            y0.x = f1a * (float)accA[mi][ni][0] + f2a * (float)accB[mi][ni][0];
            y0.y = f1a * (float)accA[mi][ni][1] + f2a * (float)accB[mi][ni][1];
            y1.x = f1b * (float)accA[mi][ni][2] + f2b * (float)accB[mi][ni][2];
            y1.y = f1b * (float)accA[mi][ni][3] + f2b * (float)accB[mi][ni][3];
            *reinterpret_cast<float2*>(o0 + col) = y0;
            *reinterpret_cast<float2*>(o1 + col) = y1;
        }
    }
}

// ============================================================================
// Host
// ============================================================================
extern "C" void kernel_launch(void* const* d_in, const int* in_sizes, int n_in,
                              void* d_out, int out_size) {
    const float* x = (const float*)d_in[0];
    const int* w32 = (const int*)d_in[1];     // int8 weights delivered as int32
    const float* scaler = (const float*)d_in[2];
    float* out = (float*)d_out;

    void* p_w = nullptr;
    cudaGetSymbolAddress(&p_w, g_w);

    prep_kernel<<<REPACK_BLOCKS + QUANT_BLOCKS, 256>>>(x, (const int4*)w32, (uint4*)p_w);

    cudaFuncSetAttribute(gemm_kernel, cudaFuncAttributeMaxDynamicSharedMemorySize, SMEM_BYTES);
    gemm_kernel<<<NTILES, 256, SMEM_BYTES>>>(scaler, out);
}

// round 15
// speedup vs baseline: 1.1520x; 1.0006x over previous
#include <cuda_runtime.h>
#include <cuda_bf16.h>
#include <cstdint>

// ============================================================================
// y[M,N] = x[M,K] @ W[N,K]^T * scaler ; x fp32, W int8 (delivered as int32),
// out fp32.
// x -> s1*a + s2*b (two int8 planes, per-row scales); W repacked int32->int8.
// Two int8 mma.sync passes, int32 accumulators, fp32 combine in epilogue.
// FINAL champion (Round 8 config; re-confirmed Rounds 13 & 14 at 2533/2521us):
//   - 256-thread CTAs (BM=64 x BN=128), 2 CTAs/SM, 5-stage cp.async pipeline
//   - GEMM at ~100% of the legacy-IMMA ceiling (1024 MAC/cyc/SM, rt=16/SMSP;
//     ncu tensor% reads ~52 because its peak is the 2x native tcgen05 rate,
//     unreachable here: plain-sm_100 ptxas rejects tcgen05.ld -> no TMEM
//     readback -> no tcgen05 epilogue)
//   - instruction count (1.8e8 s8-mma) minimal for rel_err < 1e-3 on this ISA
//   - measured deviations (ldmatrix, fp16 HMMA, scale-prefetch, 512-thr CTA)
//     all regressed; this configuration is the measured optimum
// ============================================================================
#define M_TOTAL 8192
#define N_TOTAL 11008
#define K_TOTAL 4096

#define BM 64
#define BN 128
#define BK 64
#define KITERS (K_TOTAL / BK)     // 64
#define GRID_N (N_TOTAL / BN)     // 86
#define GRID_M (M_TOTAL / BM)     // 128
#define NTILES (GRID_N * GRID_M)  // 11008

#define NS 5                       // pipeline stages
#define PITCH 80                   // smem row pitch (bytes): conflict-free quad pattern
#define A_TILE_BYTES (BM * PITCH)  // 5120 per A plane
#define B_TILE_BYTES (BN * PITCH)  // 10240
#define STAGE_BYTES (2 * A_TILE_BYTES + B_TILE_BYTES)   // 20480
#define SMEM_BYTES (NS * STAGE_BYTES)                   // 102400 -> 2 CTAs/SM

#define REPACK_BLOCKS 11008        // 256 thr, 16 int32 each
#define QUANT_BLOCKS  (M_TOTAL / 2) // 256 thr, 2 rows per block

// ============================================================================
// Device scratch (static globals: allocation-guard safe)
// ============================================================================
__device__ int8_t g_qa[(size_t)M_TOTAL * K_TOTAL];   // x hi plane
__device__ int8_t g_qb[(size_t)M_TOTAL * K_TOTAL];   // x lo (residual) plane
__device__ int8_t g_w[(size_t)N_TOTAL * K_TOTAL];    // weights repacked to int8
__device__ float2 g_s[M_TOTAL];                      // {s1, s2} per row

// ============================================================================
// PTX helpers (sm_80-level only: compiles on plain sm_100 target)
// ============================================================================
__device__ __forceinline__ uint32_t smem_u32(const void* p) {
    uint32_t a;
    asm("{ .reg .u64 t; cvta.to.shared.u64 t, %1; cvt.u32.u64 %0, t; }" : "=r"(a) : "l"(p));
    return a;
}

__device__ __forceinline__ void cp_async16(uint32_t saddr, const void* gaddr) {
    asm volatile("cp.async.cg.shared.global [%0], [%1], 16;" :: "r"(saddr), "l"(gaddr));
}
#define CP_COMMIT() asm volatile("cp.async.commit_group;")
#define CP_WAIT(n)  asm volatile("cp.async.wait_group %0;" :: "n"(n))

__device__ __forceinline__ uint32_t lds32(uint32_t a) {
    uint32_t v;
    asm volatile("ld.shared.b32 %0, [%1];" : "=r"(v) : "r"(a));
    return v;
}

__device__ __forceinline__ void mma_s8(int* c, uint32_t a0, uint32_t a1, uint32_t a2, uint32_t a3,
                                       uint32_t b0, uint32_t b1) {
    asm volatile(
        "mma.sync.aligned.m16n8k32.row.col.s32.s8.s8.s32 "
        "{%0,%1,%2,%3}, {%4,%5,%6,%7}, {%8,%9}, {%0,%1,%2,%3};"
        : "+r"(c[0]), "+r"(c[1]), "+r"(c[2]), "+r"(c[3])
        : "r"(a0), "r"(a1), "r"(a2), "r"(a3), "r"(b0), "r"(b1));
}

// ============================================================================
// Fused prep kernel: blocks [0, REPACK_BLOCKS) repack W int32->int8,
// blocks [REPACK_BLOCKS, +QUANT_BLOCKS) quantize x into two int8 planes.
// ============================================================================
__global__ void __launch_bounds__(256) prep_kernel(const float* __restrict__ x,
                                                   const int4* __restrict__ w32,
                                                   uint4* __restrict__ w8) {
    const int blk = blockIdx.x;
    const int tid = threadIdx.x;

    if (blk < REPACK_BLOCKS) {
        const uint32_t i = blk * 256 + tid;
        const int4* src = w32 + (size_t)i * 4;
        uint32_t packed[4];
#pragma unroll
        for (int j = 0; j < 4; j++) {
            int4 v = src[j];
            packed[j] = ((uint32_t)v.x & 0xFFu)
                      | (((uint32_t)v.y & 0xFFu) << 8)
                      | (((uint32_t)v.z & 0xFFu) << 16)
                      | (((uint32_t)v.w & 0xFFu) << 24);
        }
        w8[i] = make_uint4(packed[0], packed[1], packed[2], packed[3]);
        return;
    }

    // ---- quantization: 2 rows per block, 128 threads per row ----
    const int qb = blk - REPACK_BLOCKS;
    const int half = tid >> 7;
    const int tl = tid & 127;
    const int row = qb * 2 + half;
    const int lane = tid & 31;
    const int wid = tid >> 5;

    const float4* xr = reinterpret_cast<const float4*>(x + (size_t)row * K_TOTAL) + tl * 8;
    float4 v[8];
#pragma unroll
    for (int i = 0; i < 8; i++) v[i] = xr[i];

    float am = 0.0f;
#pragma unroll
    for (int i = 0; i < 8; i++) {
        am = fmaxf(am, fabsf(v[i].x)); am = fmaxf(am, fabsf(v[i].y));
        am = fmaxf(am, fabsf(v[i].z)); am = fmaxf(am, fabsf(v[i].w));
    }
#pragma unroll
    for (int off = 16; off > 0; off >>= 1)
        am = fmaxf(am, __shfl_xor_sync(0xFFFFFFFFu, am, off));

    __shared__ float red[8];
    if (lane == 0) red[wid] = am;
    __syncthreads();
    {
        const int base = half * 4;
        am = fmaxf(fmaxf(red[base + 0], red[base + 1]),
                   fmaxf(red[base + 2], red[base + 3]));
    }
    am = fmaxf(am, 1e-20f);

    const float s1 = am * (1.0f / 126.0f);
    const float inv1 = 1.0f / s1;
    const float s2 = s1 * (1.0f / 252.0f);
    const float inv2 = 1.0f / s2;

    uint32_t wa[8], wb[8];
#pragma unroll
    for (int i = 0; i < 8; i++) {
        float f[4] = {v[i].x, v[i].y, v[i].z, v[i].w};
        uint32_t pa = 0, pb = 0;
#pragma unroll
        for (int j = 0; j < 4; j++) {
            int ai = __float2int_rn(f[j] * inv1);
            float r = fmaf(-s1, (float)ai, f[j]);
            int bi = __float2int_rn(r * inv2);
            pa |= ((uint32_t)ai & 0xFFu) << (8 * j);
            pb |= ((uint32_t)bi & 0xFFu) << (8 * j);
        }
        wa[i] = pa; wb[i] = pb;
    }
    uint4* da = reinterpret_cast<uint4*>(g_qa + (size_t)row * K_TOTAL) + tl * 2;
    uint4* db = reinterpret_cast<uint4*>(g_qb + (size_t)row * K_TOTAL) + tl * 2;
    da[0] = make_uint4(wa[0], wa[1], wa[2], wa[3]);
    da[1] = make_uint4(wa[4], wa[5], wa[6], wa[7]);
    db[0] = make_uint4(wb[0], wb[1], wb[2], wb[3]);
    db[1] = make_uint4(wb[4], wb[5], wb[6], wb[7]);
    if (tl == 0) g_s[row] = make_float2(s1, s2);
}

// ============================================================================
// GEMM: 256 threads, 8 warps (2m x 4n), warp tile 32x32, 5-stage pipeline,
// 2 CTAs/SM. Per thread per stage: 4 cp.async (A_hi, A_lo, B row r, B row r+64)
// ============================================================================
__global__ void __launch_bounds__(256, 2) gemm_kernel(
    const float* __restrict__ scaler_ptr,
    float* __restrict__ out)
{
    extern __shared__ char dsm[];
    const uint32_t sb = smem_u32(dsm);

    const int tid = threadIdx.x;
    const int wid = tid >> 5;
    const int lane = tid & 31;
    const int g = lane >> 2;        // groupID (0..7)
    const int t = lane & 3;         // thread-in-group (0..3)

    const int warp_m = (wid & 1) * 32;      // 0,32
    const int warp_n = (wid >> 1) * 32;     // 0,32,64,96

    // ---- supertiled rasterization: groups of 8 n-cols, 128 m-tiles fastest ----
    const int b = blockIdx.x;
    const int grp = b >> 10;                // / (8 * GRID_M) = 1024
    const int rem = b & 1023;
    const int gcols = min(8, GRID_N - grp * 8);
    const int nt = grp * 8 + rem % gcols;
    const int mt = rem / gcols;

    const int m0 = mt * BM;
    const int n0 = nt * BN;

    const int8_t* gAh = g_qa + (size_t)m0 * K_TOTAL;
    const int8_t* gAl = g_qb + (size_t)m0 * K_TOTAL;
    const int8_t* gB  = g_w  + (size_t)n0 * K_TOTAL;

    // cp.async mapping: A planes: 64 rows x 4 chunks = 256 = one per thread.
    // B: 128 rows x 4 chunks = 512 = two per thread (rows r and r+64).
    const int rr = tid >> 2;                // 0..63
    const int qq = (tid & 3) * 16;
    const uint32_t sA_off = rr * PITCH + qq;
    const uint32_t sB_off2 = sA_off + 64 * PITCH;
    const size_t gA_off = (size_t)rr * K_TOTAL + qq;
    const size_t gB_off2 = gA_off + (size_t)64 * K_TOTAL;

    int accA[2][4][4];
    int accB[2][4][4];
#pragma unroll
    for (int mi = 0; mi < 2; mi++)
#pragma unroll
        for (int ni = 0; ni < 4; ni++)
#pragma unroll
            for (int q = 0; q < 4; q++) { accA[mi][ni][q] = 0; accB[mi][ni][q] = 0; }

    // ---- prologue: fill stages 0..NS-2 ----
#pragma unroll
    for (int s = 0; s < NS - 1; s++) {
        const int k0 = s * BK;
        const uint32_t so = sb + s * STAGE_BYTES;
        cp_async16(so + sA_off,                      gAh + gA_off + k0);
        cp_async16(so + A_TILE_BYTES + sA_off,       gAl + gA_off + k0);
        cp_async16(so + 2 * A_TILE_BYTES + sA_off,   gB  + gA_off + k0);
        cp_async16(so + 2 * A_TILE_BYTES + sB_off2,  gB  + gB_off2 + k0);
        CP_COMMIT();
    }

    for (int kt = 0; kt < KITERS; kt++) {
        CP_WAIT(NS - 2);       // stage kt data complete (this thread's copies)
        __syncthreads();       // stage kt visible to all; stage (kt-1)%NS free

        const int kl = kt + NS - 1;
        if (kl < KITERS) {
            const int k0 = kl * BK;
            const uint32_t so = sb + (kl % NS) * STAGE_BYTES;
            cp_async16(so + sA_off,                      gAh + gA_off + k0);
            cp_async16(so + A_TILE_BYTES + sA_off,       gAl + gA_off + k0);
            cp_async16(so + 2 * A_TILE_BYTES + sA_off,   gB  + gA_off + k0);
            cp_async16(so + 2 * A_TILE_BYTES + sB_off2,  gB  + gB_off2 + k0);
        }
        CP_COMMIT();           // uniform group counting even when empty

        const uint32_t sA  = sb + (kt % NS) * STAGE_BYTES;
        const uint32_t sAl = sA + A_TILE_BYTES;
        const uint32_t sB  = sA + 2 * A_TILE_BYTES;

#pragma unroll
        for (int ks = 0; ks < 2; ks++) {
            const uint32_t kb = ks * 32 + t * 4;
            uint32_t bfr[4][2];
#pragma unroll
            for (int ni = 0; ni < 4; ni++) {
                const uint32_t ad = sB + (uint32_t)(warp_n + ni * 8 + g) * PITCH + kb;
                bfr[ni][0] = lds32(ad);
                bfr[ni][1] = lds32(ad + 16);
            }
#pragma unroll
            for (int mi = 0; mi < 2; mi++) {
                const uint32_t ro = (uint32_t)(warp_m + mi * 16 + g) * PITCH + kb;
                uint32_t a0 = lds32(sA + ro);
                uint32_t a1 = lds32(sA + ro + 8 * PITCH);
                uint32_t a2 = lds32(sA + ro + 16);
                uint32_t a3 = lds32(sA + ro + 8 * PITCH + 16);
#pragma unroll
                for (int ni = 0; ni < 4; ni++)
                    mma_s8(accA[mi][ni], a0, a1, a2, a3, bfr[ni][0], bfr[ni][1]);
                uint32_t l0 = lds32(sAl + ro);
                uint32_t l1 = lds32(sAl + ro + 8 * PITCH);
                uint32_t l2 = lds32(sAl + ro + 16);
                uint32_t l3 = lds32(sAl + ro + 8 * PITCH + 16);
#pragma unroll
                for (int ni = 0; ni < 4; ni++)
                    mma_s8(accB[mi][ni], l0, l1, l2, l3, bfr[ni][0], bfr[ni][1]);
            }
        }
    }

    // ---- epilogue ----
    const float sc = *scaler_ptr;
#pragma unroll
    for (int mi = 0; mi < 2; mi++) {
        const int gr0 = m0 + warp_m + mi * 16 + g;
        const int gr1 = gr0 + 8;
        const float2 sv0 = __ldg(&g_s[gr0]);
        const float2 sv1 = __ldg(&g_s[gr1]);
        const float f1a = sc * sv0.x, f2a = sc * sv0.y;
        const float f1b = sc * sv1.x, f2b = sc * sv1.y;
        float* o0 = out + (size_t)gr0 * N_TOTAL + n0 + warp_n;
        float* o1 = out + (size_t)gr1 * N_TOTAL + n0 + warp_n;
#pragma unroll
        for (int ni = 0; ni < 4; ni++) {
            const int col = ni * 8 + t * 2;
            float2 y0, y1;
            y0.x = f1a * (float)accA[mi][ni][0] + f2a * (float)accB[mi][ni][0];
            y0.y = f1a * (float)accA[mi][ni][1] + f2a * (float)accB[mi][ni][1];
            y1.x = f1b * (float)accA[mi][ni][2] + f2b * (float)accB[mi][ni][2];
            y1.y = f1b * (float)accA[mi][ni][3] + f2b * (float)accB[mi][ni][3];
            *reinterpret_cast<float2*>(o0 + col) = y0;
            *reinterpret_cast<float2*>(o1 + col) = y1;
        }
    }
}

// ============================================================================
// Host
// ============================================================================
extern "C" void kernel_launch(void* const* d_in, const int* in_sizes, int n_in,
                              void* d_out, int out_size) {
    const float* x = (const float*)d_in[0];
    const int* w32 = (const int*)d_in[1];     // int8 weights delivered as int32
    const float* scaler = (const float*)d_in[2];
    float* out = (float*)d_out;

    void* p_w = nullptr;
    cudaGetSymbolAddress(&p_w, g_w);

    prep_kernel<<<REPACK_BLOCKS + QUANT_BLOCKS, 256>>>(x, (const int4*)w32, (uint4*)p_w);

    cudaFuncSetAttribute(gemm_kernel, cudaFuncAttributeMaxDynamicSharedMemorySize, SMEM_BYTES);
    gemm_kernel<<<NTILES, 256, SMEM_BYTES>>>(scaler, out);
}